// round 4
// baseline (speedup 1.0000x reference)
#include <cuda_runtime.h>

typedef unsigned long long u64;
typedef unsigned int u32;

// ---- packed f32x2 helpers ----
__device__ __forceinline__ u64 pack2(float lo, float hi) {
    u64 r; asm("mov.b64 %0, {%1, %2};" : "=l"(r) : "f"(lo), "f"(hi)); return r;
}
__device__ __forceinline__ void unpack2(u64 v, float& lo, float& hi) {
    asm("mov.b64 {%0, %1}, %2;" : "=f"(lo), "=f"(hi) : "l"(v));
}
__device__ __forceinline__ u64 fma2(u64 a, u64 b, u64 c) {
    u64 d; asm("fma.rn.f32x2 %0, %1, %2, %3;" : "=l"(d) : "l"(a), "l"(b), "l"(c)); return d;
}
// load 4 consecutive floats from smem as two f32x2 pairs (bit-identical, no MOVs)
__device__ __forceinline__ void lds_pair2(u32 addr, u64& p0, u64& p1) {
    asm volatile("ld.shared.v2.u64 {%0, %1}, [%2];" : "=l"(p0), "=l"(p1) : "r"(addr));
}
__device__ __forceinline__ u32 smem_u32(const void* p) {
    u32 a; asm("{ .reg .u64 t; cvta.to.shared.u64 t, %1; cvt.u32.u64 %0, t; }" : "=r"(a) : "l"(p));
    return a;
}

// ---- accurate transcendentals (MUFU EX2 ~2^-22, RCP ~1 ulp) ----
__device__ __forceinline__ float ex2f(float x) { float r; asm("ex2.approx.f32 %0, %1;" : "=f"(r) : "f"(x)); return r; }
__device__ __forceinline__ float rcpf(float x) { float r; asm("rcp.approx.f32 %0, %1;" : "=f"(r) : "f"(x)); return r; }
__device__ __forceinline__ float sigf(float x)   { return rcpf(1.0f + ex2f(-1.4426950408889634f * x)); }
__device__ __forceinline__ float tanhf_(float x) { return fmaf(-2.0f, rcpf(1.0f + ex2f(2.8853900817779268f * x)), 1.0f); }

#define TSTEPS 512
#define ROWS_PER_CTA 4   // 8 warps: warp pair (2r, 2r+1) per row

// Warp PAIR per batch row. Lane j owns hidden unit j.
//   warp A (even wid): gates i (0) and f (1)
//   warp B (odd  wid): gates g (2) and o (3), owns c state, writes h
// Each warp holds 2 gates x 16 k-pairs = 32 u64 = 64 weight regs.
// Gate accumulators are f32x2 over k-pairs; horizontal add at the end.
__global__ void __launch_bounds__(32 * 2 * ROWS_PER_CTA, 2)
lstm_kernel(const float* __restrict__ x,
            const float* __restrict__ W_ih,
            const float* __restrict__ W_hh,
            const float* __restrict__ b_ih,
            const float* __restrict__ b_hh,
            const float* __restrict__ W_fc,
            const float* __restrict__ b_fc,
            float* __restrict__ out, int B)
{
    __shared__ __align__(16) float hrow[ROWS_PER_CTA][32];
    __shared__ u64 xchg[ROWS_PER_CTA][32];

    const int wid  = threadIdx.x >> 5;
    const int lane = threadIdx.x & 31;
    const int pair = wid >> 1;          // 0..3
    const int isB  = wid & 1;
    const int barid = 1 + pair;         // named barriers 1..4 (0 = syncthreads)
    const int b    = blockIdx.x * ROWS_PER_CTA + pair;

    // gates handled by this warp
    const int g0 = isB ? 2 : 0;
    const int g1 = isB ? 3 : 1;

    // ---- weights: 2 gates x 16 k-pairs ----
    u64 w0[16], w1[16];
#pragma unroll
    for (int q = 0; q < 16; q++) {
        const float* r0 = W_hh + (g0 * 32 + lane) * 32 + 2 * q;
        const float* r1 = W_hh + (g1 * 32 + lane) * 32 + 2 * q;
        w0[q] = pack2(r0[0], r0[1]);
        w1[q] = pack2(r1[0], r1[1]);
    }
    const float wih0  = W_ih[g0 * 32 + lane];
    const float wih1  = W_ih[g1 * 32 + lane];
    const float bias0 = b_ih[g0 * 32 + lane] + b_hh[g0 * 32 + lane];
    const float bias1 = b_ih[g1 * 32 + lane] + b_hh[g1 * 32 + lane];

    if (!isB) hrow[pair][lane] = 0.0f;
    __syncthreads();

    const u32 haddr = smem_u32(&hrow[pair][0]);
    const u64* xch  = xchg[pair];

    float c = 0.0f;   // live only in B warps
    const float* xb = x + (size_t)b * TSTEPS;

#pragma unroll 1
    for (int tc = 0; tc < TSTEPS; tc += 32) {
        const float xchunk = xb[tc + lane];
#pragma unroll 1
        for (int tt = 0; tt < 32; tt++) {
            const float xv = __shfl_sync(0xffffffffu, xchunk, tt);

            // ---- recurrence: acc over 16 h-pairs, packed f32x2 ----
            u64 p0 = 0ull, p1 = 0ull;
#pragma unroll
            for (int q = 0; q < 8; q++) {
                u64 ha, hb;
                lds_pair2(haddr + q * 16, ha, hb);   // {h4q,h4q+1},{h4q+2,h4q+3}
                p0 = fma2(w0[2 * q],     ha, p0);
                p1 = fma2(w1[2 * q],     ha, p1);
                p0 = fma2(w0[2 * q + 1], hb, p0);
                p1 = fma2(w1[2 * q + 1], hb, p1);
            }
            float l0, h0, l1, h1;
            unpack2(p0, l0, h0);
            unpack2(p1, l1, h1);
            const float a0 = fmaf(xv, wih0, bias0) + (l0 + h0);
            const float a1 = fmaf(xv, wih1, bias1) + (l1 + h1);

            if (!isB) {
                // A: sigmoid(i), sigmoid(f) -> publish
                const float si = sigf(a0);
                const float sf = sigf(a1);
                ((u64*)xch)[lane] = pack2(si, sf);
                asm volatile("bar.sync %0, 64;" :: "r"(barid) : "memory");  // #1
                asm volatile("bar.sync %0, 64;" :: "r"(barid) : "memory");  // #2 (h ready)
            } else {
                // B: tanh(g), sigmoid(o); then consume A's gates
                const float tg = tanhf_(a0);
                const float so = sigf(a1);
                asm volatile("bar.sync %0, 64;" :: "r"(barid) : "memory");  // #1
                float si, sf;
                unpack2(xch[lane], si, sf);
                c = fmaf(sf, c, si * tg);
                const float h = so * tanhf_(c);
                hrow[pair][lane] = h;
                asm volatile("bar.sync %0, 64;" :: "r"(barid) : "memory");  // #2
            }
        }
    }

    // ---- final head (A warp of each pair): out[b] = dot(h, W_fc) + b_fc ----
    if (!isB) {
        float p = hrow[pair][lane] * W_fc[lane];
#pragma unroll
        for (int off = 16; off; off >>= 1)
            p += __shfl_xor_sync(0xffffffffu, p, off);
        if (lane == 0 && b < B) out[b] = p + b_fc[0];
    }
}

extern "C" void kernel_launch(void* const* d_in, const int* in_sizes, int n_in,
                              void* d_out, int out_size)
{
    const float* x    = (const float*)d_in[0];
    const float* W_ih = (const float*)d_in[1];
    const float* W_hh = (const float*)d_in[2];
    const float* b_ih = (const float*)d_in[3];
    const float* b_hh = (const float*)d_in[4];
    const float* W_fc = (const float*)d_in[5];
    const float* b_fc = (const float*)d_in[6];
    float* out = (float*)d_out;

    int B = in_sizes[0] / TSTEPS;  // x is [B, 512, 1]
    int blocks = (B + ROWS_PER_CTA - 1) / ROWS_PER_CTA;
    lstm_kernel<<<blocks, 32 * 2 * ROWS_PER_CTA>>>(x, W_ih, W_hh, b_ih, b_hh, W_fc, b_fc, out, B);
}

// round 5
// speedup vs baseline: 1.8941x; 1.8941x over previous
#include <cuda_runtime.h>

typedef unsigned long long u64;
typedef unsigned int u32;

// ---- packed f32x2 helpers (Blackwell packed FP32; PTX-only, ptxas never fuses) ----
__device__ __forceinline__ u64 pack2(float lo, float hi) {
    u64 r; asm("mov.b64 %0, {%1, %2};" : "=l"(r) : "f"(lo), "f"(hi)); return r;
}
__device__ __forceinline__ void unpack2(u64 v, float& lo, float& hi) {
    asm("mov.b64 {%0, %1}, %2;" : "=f"(lo), "=f"(hi) : "l"(v));
}
__device__ __forceinline__ u64 fma2(u64 a, u64 b, u64 c) {
    u64 d; asm("fma.rn.f32x2 %0, %1, %2, %3;" : "=l"(d) : "l"(a), "l"(b), "l"(c)); return d;
}
__device__ __forceinline__ u64 add2(u64 a, u64 b) {
    u64 d; asm("add.rn.f32x2 %0, %1, %2;" : "=l"(d) : "l"(a), "l"(b)); return d;
}
// one LDS.128: loads two consecutive u64 smem words ({h2q,h2q},{h2q+1,h2q+1})
__device__ __forceinline__ void lds2(u32 addr, u64& p0, u64& p1) {
    asm volatile("ld.shared.v2.u64 {%0, %1}, [%2];" : "=l"(p0), "=l"(p1) : "r"(addr));
}
__device__ __forceinline__ u32 smem_u32(const void* p) {
    u32 a; asm("{ .reg .u64 t; cvta.to.shared.u64 t, %1; cvt.u32.u64 %0, t; }" : "=r"(a) : "l"(p));
    return a;
}

// ---- accurate fast transcendentals (MUFU EX2 ~2^-22 rel err, RCP ~1 ulp) ----
__device__ __forceinline__ float ex2f(float x) { float r; asm("ex2.approx.f32 %0, %1;" : "=f"(r) : "f"(x)); return r; }
__device__ __forceinline__ float rcpf(float x) { float r; asm("rcp.approx.f32 %0, %1;" : "=f"(r) : "f"(x)); return r; }
__device__ __forceinline__ float sigf(float x)   { return rcpf(1.0f + ex2f(-1.4426950408889634f * x)); }
__device__ __forceinline__ float tanhf_(float x) { return fmaf(-2.0f, rcpf(1.0f + ex2f(2.8853900817779268f * x)), 1.0f); }

#define TSTEPS 512
#define WARPS_PER_CTA 4

// One warp per batch row. Lane j owns hidden unit j.
// Gates packed (i,f)->a01, (g,o)->a23 as f32x2; two accumulation chains each
// (even/odd k) to halve the fma2 dependency depth. h broadcast via ping-pong
// SMEM buffer of duplicated {h,h} u64 words -> LDS.128 loads, ONE syncwarp/step.
__global__ void __launch_bounds__(32 * WARPS_PER_CTA, 3)
lstm_kernel(const float* __restrict__ x,
            const float* __restrict__ W_ih,
            const float* __restrict__ W_hh,
            const float* __restrict__ b_ih,
            const float* __restrict__ b_hh,
            const float* __restrict__ W_fc,
            const float* __restrict__ b_fc,
            float* __restrict__ out, int B)
{
    __shared__ __align__(16) u64 hbuf[2][WARPS_PER_CTA][32];   // {h,h} per unit

    const int wl   = threadIdx.x >> 5;
    const int lane = threadIdx.x & 31;
    const int b    = blockIdx.x * WARPS_PER_CTA + wl;
    if (b >= B) return;

    // ---- preload W_hh into 128 regs/lane: w01[k]={W_i[lane][k],W_f[lane][k]} ----
    u64 w01[32], w23[32];
#pragma unroll
    for (int k = 0; k < 32; k++) {
        w01[k] = pack2(W_hh[(lane)      * 32 + k], W_hh[(32 + lane) * 32 + k]);
        w23[k] = pack2(W_hh[(64 + lane) * 32 + k], W_hh[(96 + lane) * 32 + k]);
    }
    const u64 wih01  = pack2(W_ih[lane],      W_ih[32 + lane]);
    const u64 wih23  = pack2(W_ih[64 + lane], W_ih[96 + lane]);
    const u64 bias01 = pack2(b_ih[lane]      + b_hh[lane],
                             b_ih[32 + lane] + b_hh[32 + lane]);
    const u64 bias23 = pack2(b_ih[64 + lane] + b_hh[64 + lane],
                             b_ih[96 + lane] + b_hh[96 + lane]);

    float h = 0.0f, c = 0.0f;
    hbuf[0][wl][lane] = 0ull;
    __syncwarp();

    const u32 haddr0 = smem_u32(&hbuf[0][wl][0]);
    const u32 haddr1 = smem_u32(&hbuf[1][wl][0]);
    const float* xb  = x + (size_t)b * TSTEPS;

#define STEP(TT, RD, WR)                                                       \
    {                                                                          \
        const float xv = __shfl_sync(0xffffffffu, xchunk, (TT));               \
        const u64 xv2  = pack2(xv, xv);                                        \
        u64 a01 = fma2(xv2, wih01, bias01);                                    \
        u64 a23 = fma2(xv2, wih23, bias23);                                    \
        u64 e01 = 0ull, e23 = 0ull;                                            \
        _Pragma("unroll")                                                      \
        for (int q = 0; q < 16; q++) {                                         \
            u64 hk0, hk1;                                                      \
            lds2((RD) + q * 16, hk0, hk1);                                     \
            a01 = fma2(w01[2 * q],     hk0, a01);                              \
            a23 = fma2(w23[2 * q],     hk0, a23);                              \
            e01 = fma2(w01[2 * q + 1], hk1, e01);                              \
            e23 = fma2(w23[2 * q + 1], hk1, e23);                              \
        }                                                                      \
        a01 = add2(a01, e01);                                                  \
        a23 = add2(a23, e23);                                                  \
        float ai, af, ag, ao;                                                  \
        unpack2(a01, ai, af);                                                  \
        unpack2(a23, ag, ao);                                                  \
        const float ig = sigf(ai);                                             \
        const float fg = sigf(af);                                             \
        const float gg = tanhf_(ag);                                           \
        const float og = sigf(ao);                                             \
        c = fmaf(fg, c, ig * gg);                                              \
        h = og * tanhf_(c);                                                    \
        asm volatile("st.shared.u64 [%0], %1;" :: "r"((WR) + lane * 8),        \
                     "l"(pack2(h, h)) : "memory");                             \
        __syncwarp();                                                          \
    }

#pragma unroll 1
    for (int tc = 0; tc < TSTEPS; tc += 32) {
        const float xchunk = xb[tc + lane];   // coalesced 128B / warp / 32 steps
#pragma unroll 1
        for (int tt = 0; tt < 32; tt += 2) {
            STEP(tt,     haddr0, haddr1)   // read buf0, write buf1
            STEP(tt + 1, haddr1, haddr0)   // read buf1, write buf0
        }
    }
#undef STEP

    // ---- final head: out[b] = dot(h, W_fc) + b_fc ----
    float p = h * W_fc[lane];
#pragma unroll
    for (int off = 16; off; off >>= 1)
        p += __shfl_xor_sync(0xffffffffu, p, off);
    if (lane == 0) out[b] = p + b_fc[0];
}

extern "C" void kernel_launch(void* const* d_in, const int* in_sizes, int n_in,
                              void* d_out, int out_size)
{
    const float* x    = (const float*)d_in[0];
    const float* W_ih = (const float*)d_in[1];
    const float* W_hh = (const float*)d_in[2];
    const float* b_ih = (const float*)d_in[3];
    const float* b_hh = (const float*)d_in[4];
    const float* W_fc = (const float*)d_in[5];
    const float* b_fc = (const float*)d_in[6];
    float* out = (float*)d_out;

    int B = in_sizes[0] / TSTEPS;  // x is [B, 512, 1]
    int blocks = (B + WARPS_PER_CTA - 1) / WARPS_PER_CTA;
    lstm_kernel<<<blocks, 32 * WARPS_PER_CTA>>>(x, W_ih, W_hh, b_ih, b_hh, W_fc, b_fc, out, B);
}

// round 11
// speedup vs baseline: 2.0979x; 1.1076x over previous
#include <cuda_runtime.h>

typedef unsigned long long u64;
typedef unsigned int u32;

// ---- packed f32x2 helpers (PTX-only; ptxas never auto-fuses) ----
__device__ __forceinline__ u64 pack2(float lo, float hi) {
    u64 r; asm("mov.b64 %0, {%1, %2};" : "=l"(r) : "f"(lo), "f"(hi)); return r;
}
__device__ __forceinline__ void unpack2(u64 v, float& lo, float& hi) {
    asm("mov.b64 {%0, %1}, %2;" : "=f"(lo), "=f"(hi) : "l"(v));
}
__device__ __forceinline__ u64 fma2(u64 a, u64 b, u64 c) {
    u64 d; asm("fma.rn.f32x2 %0, %1, %2, %3;" : "=l"(d) : "l"(a), "l"(b), "l"(c)); return d;
}
// one LDS.128 (broadcast): 4 consecutive floats as two f32x2 pairs
__device__ __forceinline__ void lds2(u32 addr, u64& p0, u64& p1) {
    asm volatile("ld.shared.v2.u64 {%0, %1}, [%2];" : "=l"(p0), "=l"(p1) : "r"(addr));
}
__device__ __forceinline__ u32 smem_u32(const void* p) {
    u32 a; asm("{ .reg .u64 t; cvta.to.shared.u64 t, %1; cvt.u32.u64 %0, t; }" : "=r"(a) : "l"(p));
    return a;
}

// ---- MUFU primitives ----
__device__ __forceinline__ float ex2f(float x) { float r; asm("ex2.approx.f32 %0, %1;" : "=f"(r) : "f"(x)); return r; }
__device__ __forceinline__ float rcpf(float x) { float r; asm("rcp.approx.f32 %0, %1;" : "=f"(r) : "f"(x)); return r; }
// tanh for c (argument can't be pre-scaled)
__device__ __forceinline__ float tanhf_(float x) { return fmaf(-2.0f, rcpf(1.0f + ex2f(2.8853900817779268f * x)), 1.0f); }

#define TSTEPS 512
#define WARPS_PER_CTA 4

// One warp per batch row; lane j owns hidden unit j.
// Gate-major f32x2 accumulation over k-pairs: 4 independent 16-deep fma2 chains.
// h stored unduplicated (32 floats) -> 8 broadcast LDS.128 per step.
// Activation argument scales (±log2e) pre-folded into W_hh/W_ih/biases.
// Raw x chunk staged in SMEM; per step one broadcast LDS.32 + per-lane fmaf
// gives the (per-unit!) input projection.
__global__ void __launch_bounds__(32 * WARPS_PER_CTA, 3)
lstm_kernel(const float* __restrict__ x,
            const float* __restrict__ W_ih,
            const float* __restrict__ W_hh,
            const float* __restrict__ b_ih,
            const float* __restrict__ b_hh,
            const float* __restrict__ W_fc,
            const float* __restrict__ b_fc,
            float* __restrict__ out, int B)
{
    __shared__ __align__(16) float hbuf[2][WARPS_PER_CTA][32];  // plain h
    __shared__ __align__(16) float xsm[WARPS_PER_CTA][32];      // raw x chunk

    const int wl   = threadIdx.x >> 5;
    const int lane = threadIdx.x & 31;
    const int b    = blockIdx.x * WARPS_PER_CTA + wl;
    if (b >= B) return;

    // sigmoid(a) = rcp(1 + ex2(-log2e * a)); tanh(a) = fma(-2, rcp(1 + ex2(2*log2e*a)), 1)
    const float SG0 = -1.4426950408889634f;  // i (sigmoid)
    const float SG1 = -1.4426950408889634f;  // f (sigmoid)
    const float SG2 =  2.8853900817779268f;  // g (tanh)
    const float SG3 = -1.4426950408889634f;  // o (sigmoid)

    // ---- weights, gate-major k-pairs: wg[q] = {S*W[g][lane][2q], S*W[g][lane][2q+1]} ----
    u64 w0[16], w1[16], w2[16], w3[16];
#pragma unroll
    for (int q = 0; q < 16; q++) {
        const float* r0 = W_hh + (lane)      * 32 + 2 * q;
        const float* r1 = W_hh + (32 + lane) * 32 + 2 * q;
        const float* r2 = W_hh + (64 + lane) * 32 + 2 * q;
        const float* r3 = W_hh + (96 + lane) * 32 + 2 * q;
        w0[q] = pack2(SG0 * r0[0], SG0 * r0[1]);
        w1[q] = pack2(SG1 * r1[0], SG1 * r1[1]);
        w2[q] = pack2(SG2 * r2[0], SG2 * r2[1]);
        w3[q] = pack2(SG3 * r3[0], SG3 * r3[1]);
    }
    const float wih0 = SG0 * W_ih[lane],      bia0 = SG0 * (b_ih[lane]      + b_hh[lane]);
    const float wih1 = SG1 * W_ih[32 + lane], bia1 = SG1 * (b_ih[32 + lane] + b_hh[32 + lane]);
    const float wih2 = SG2 * W_ih[64 + lane], bia2 = SG2 * (b_ih[64 + lane] + b_hh[64 + lane]);
    const float wih3 = SG3 * W_ih[96 + lane], bia3 = SG3 * (b_ih[96 + lane] + b_hh[96 + lane]);

    float h = 0.0f, c = 0.0f;
    hbuf[0][wl][lane] = 0.0f;

    const u32 haddr0 = smem_u32(&hbuf[0][wl][0]);
    const u32 haddr1 = smem_u32(&hbuf[1][wl][0]);
    const float* xsp = &xsm[wl][0];
    const float* xb  = x + (size_t)b * TSTEPS;

#define STEP(TT, RD, WRP)                                                      \
    {                                                                          \
        const float xv = xsp[(TT)];             /* broadcast LDS.32 */         \
        u64 a0 = 0ull, a1 = 0ull, a2 = 0ull, a3 = 0ull;                        \
        _Pragma("unroll")                                                      \
        for (int j = 0; j < 8; j++) {                                          \
            u64 pA, pB;                                                        \
            lds2((RD) + j * 16, pA, pB);        /* {h4j,h4j+1},{h4j+2,h4j+3} */\
            a0 = fma2(w0[2 * j], pA, a0);                                      \
            a1 = fma2(w1[2 * j], pA, a1);                                      \
            a2 = fma2(w2[2 * j], pA, a2);                                      \
            a3 = fma2(w3[2 * j], pA, a3);                                      \
            a0 = fma2(w0[2 * j + 1], pB, a0);                                  \
            a1 = fma2(w1[2 * j + 1], pB, a1);                                  \
            a2 = fma2(w2[2 * j + 1], pB, a2);                                  \
            a3 = fma2(w3[2 * j + 1], pB, a3);                                  \
        }                                                                      \
        float l0, u0_, l1, u1_, l2, u2_, l3, u3_;                              \
        unpack2(a0, l0, u0_);                                                  \
        unpack2(a1, l1, u1_);                                                  \
        unpack2(a2, l2, u2_);                                                  \
        unpack2(a3, l3, u3_);                                                  \
        const float s0 = fmaf(xv, wih0, bia0) + (l0 + u0_);                    \
        const float s1 = fmaf(xv, wih1, bia1) + (l1 + u1_);                    \
        const float s2 = fmaf(xv, wih2, bia2) + (l2 + u2_);                    \
        const float s3 = fmaf(xv, wih3, bia3) + (l3 + u3_);                    \
        const float ig = rcpf(1.0f + ex2f(s0));                                \
        const float fg = rcpf(1.0f + ex2f(s1));                                \
        const float gg = fmaf(-2.0f, rcpf(1.0f + ex2f(s2)), 1.0f);             \
        const float og = rcpf(1.0f + ex2f(s3));                                \
        c = fmaf(fg, c, ig * gg);                                              \
        h = og * tanhf_(c);                                                    \
        (WRP)[lane] = h;                        /* STS.32 */                   \
        __syncwarp();                                                          \
    }

#pragma unroll 1
    for (int tc = 0; tc < TSTEPS; tc += 32) {
        xsm[wl][lane] = xb[tc + lane];           // coalesced 128B per warp
        __syncwarp();

#pragma unroll 1
        for (int tt = 0; tt < 32; tt += 2) {
            STEP(tt,     haddr0, (&hbuf[1][wl][0]))   // read buf0, write buf1
            STEP(tt + 1, haddr1, (&hbuf[0][wl][0]))   // read buf1, write buf0
        }
    }
#undef STEP

    // ---- final head: out[b] = dot(h, W_fc) + b_fc ----
    float p = h * W_fc[lane];
#pragma unroll
    for (int off = 16; off; off >>= 1)
        p += __shfl_xor_sync(0xffffffffu, p, off);
    if (lane == 0) out[b] = p + b_fc[0];
}

extern "C" void kernel_launch(void* const* d_in, const int* in_sizes, int n_in,
                              void* d_out, int out_size)
{
    const float* x    = (const float*)d_in[0];
    const float* W_ih = (const float*)d_in[1];
    const float* W_hh = (const float*)d_in[2];
    const float* b_ih = (const float*)d_in[3];
    const float* b_hh = (const float*)d_in[4];
    const float* W_fc = (const float*)d_in[5];
    const float* b_fc = (const float*)d_in[6];
    float* out = (float*)d_out;

    int B = in_sizes[0] / TSTEPS;  // x is [B, 512, 1]
    int blocks = (B + WARPS_PER_CTA - 1) / WARPS_PER_CTA;
    lstm_kernel<<<blocks, 32 * WARPS_PER_CTA>>>(x, W_ih, W_hh, b_ih, b_hh, W_fc, b_fc, out, B);
}